// round 4
// baseline (speedup 1.0000x reference)
#include <cuda_runtime.h>
#include <math.h>

#define QN  32
#define DN  4096
#define DIM 384
#define H2  192

// Scratch (device globals: allocation-free per harness rules)
__device__ float g_B[DN * DIM];  // doc_dense @ W1[384:768]
__device__ float g_A[QN * DIM];  // query_dense @ W1[0:384] + b1

// ---------------------------------------------------------------------------
// Kernel 1: precompute A and B.
// Blocks 0..127: 32 doc rows each. Block 128: the 32 query rows.
// Each block: X(32x384) @ W(384x384) -> out(32x384). Static 48KB smem.
// ---------------------------------------------------------------------------
__global__ void __launch_bounds__(256)
k_precompute(const float* __restrict__ qd,
             const float* __restrict__ dd,
             const float* __restrict__ W1,
             const float* __restrict__ b1)
{
    __shared__ float Xs[32 * DIM];   // 48 KB
    const int blk = blockIdx.x;
    const int tid = threadIdx.x;

    const float* X;
    const float* Wp;
    float* out;
    bool isQ;
    if (blk < DN / 32) {
        X   = dd + blk * 32 * DIM;
        Wp  = W1 + DIM * DIM;        // W1 rows [384:768]
        out = g_B + blk * 32 * DIM;
        isQ = false;
    } else {
        X   = qd;
        Wp  = W1;                    // W1 rows [0:384]
        out = g_A;
        isQ = true;
    }

    for (int e = tid; e < 32 * DIM; e += 256) Xs[e] = X[e];
    __syncthreads();

    const int ty = tid >> 5;         // 0..7  -> 4 rows each
    const int tx = tid & 31;         // 0..31 -> 12 cols each
    const int m0 = ty * 4;
    const int n0 = tx * 12;

    float acc[4][12];
#pragma unroll
    for (int i = 0; i < 4; i++)
#pragma unroll
        for (int j = 0; j < 12; j++) acc[i][j] = 0.f;

    for (int k = 0; k < DIM; k++) {
        float a[4];
#pragma unroll
        for (int i = 0; i < 4; i++) a[i] = Xs[(m0 + i) * DIM + k];
        const float4 b0  = *(const float4*)(Wp + k * DIM + n0);
        const float4 b1v = *(const float4*)(Wp + k * DIM + n0 + 4);
        const float4 b2v = *(const float4*)(Wp + k * DIM + n0 + 8);
        const float bb[12] = {b0.x, b0.y, b0.z, b0.w,
                              b1v.x, b1v.y, b1v.z, b1v.w,
                              b2v.x, b2v.y, b2v.z, b2v.w};
#pragma unroll
        for (int i = 0; i < 4; i++)
#pragma unroll
            for (int j = 0; j < 12; j++)
                acc[i][j] = fmaf(a[i], bb[j], acc[i][j]);
    }

#pragma unroll
    for (int i = 0; i < 4; i++)
#pragma unroll
        for (int j = 0; j < 12; j++) {
            float v = acc[i][j];
            if (isQ) v += b1[n0 + j];
            out[(m0 + i) * DIM + n0 + j] = v;
        }
}

// ---------------------------------------------------------------------------
// Kernel 2: dense_scores = query @ doc^T -> out[QN*DN .. 2*QN*DN)
//           sparse copy                  -> out[2*QN*DN .. 3*QN*DN)
// Grid: 64 blocks x 256 thr. Queries cached in static smem (48 KB);
// doc rows streamed from global (L2-resident, read once per block).
// Thread t handles doc (d0 + t%64), q-range [ (t/64)*8, +8 ).
// ---------------------------------------------------------------------------
__global__ void __launch_bounds__(256)
k_dense(const float* __restrict__ qd,
        const float* __restrict__ dd,
        const float* __restrict__ sparse,
        float* __restrict__ out)
{
    __shared__ float qs[32 * DIM];   // 48 KB

    const int d0  = blockIdx.x * 64;
    const int tid = threadIdx.x;

    for (int e = tid; e < 32 * DIM; e += 256) qs[e] = qd[e];
    __syncthreads();

    const int tx = tid & 63;          // doc within tile
    const int ty = tid >> 6;          // 0..3 -> 8 q's each
    const int d  = d0 + tx;
    const float* drow = dd + d * DIM;

    float acc[8];
#pragma unroll
    for (int i = 0; i < 8; i++) acc[i] = 0.f;

    for (int k = 0; k < DIM; k += 4) {
        const float4 dv4 = *(const float4*)(drow + k);
        const float dv[4] = {dv4.x, dv4.y, dv4.z, dv4.w};
#pragma unroll
        for (int t = 0; t < 4; t++)
#pragma unroll
            for (int i = 0; i < 8; i++)
                acc[i] = fmaf(qs[(ty * 8 + i) * DIM + k + t], dv[t], acc[i]);
    }

    float* outD = out + QN * DN;
    float* outS = out + 2 * QN * DN;
#pragma unroll
    for (int i = 0; i < 8; i++) {
        const int q   = ty * 8 + i;
        const int idx = q * DN + d;
        outD[idx] = acc[i];
        outS[idx] = sparse[idx];
    }
}

// ---------------------------------------------------------------------------
// Kernel 3: main fused MLP. One CTA = 1 q x 64 docs.
// Phase A: h1[64][384] = relu(A[q] + B[d] + ds*w_ds + sp*w_sp) in smem.
// Phase B: h1 @ W2 (smem-staged K-tiles of 32), 4x12 register tiles.
// Layer 3: relu, dot with W3, 16-lane shfl reduce, sigmoid, fuse, store.
// ---------------------------------------------------------------------------
__global__ void __launch_bounds__(256)
k_main(const float* __restrict__ W1,
       const float* __restrict__ W2,
       const float* __restrict__ b2,
       const float* __restrict__ W3,
       const float* __restrict__ b3,
       const float* __restrict__ sparse,
       float* __restrict__ out)
{
    extern __shared__ float s3[];
    float* h1s = s3;                         // 64*384 = 24576
    float* w2s = h1s + 64 * DIM;             // 32*192 =  6144
    float* As  = w2s + 32 * H2;              // 384
    float* wds = As  + DIM;                  // 384
    float* wsp = wds + DIM;                  // 384
    float* b2s = wsp + DIM;                  // 192
    float* w3s = b2s + H2;                   // 192
    float* dss = w3s + H2;                   // 64
    float* sps = dss + 64;                   // 64

    const int tid = threadIdx.x;
    const int blk = blockIdx.x;
    const int q   = blk >> 6;                // blk / 64
    const int d0  = (blk & 63) << 6;         // (blk % 64) * 64
    const float* outD = out + QN * DN;

    for (int e = tid; e < DIM; e += 256) {
        As[e]  = g_A[q * DIM + e];
        wds[e] = W1[768 * DIM + e];
        wsp[e] = W1[769 * DIM + e];
    }
    if (tid < H2) { b2s[tid] = b2[tid]; w3s[tid] = W3[tid]; }
    if (tid < 64) {
        const int idx = q * DN + d0 + tid;
        dss[tid] = outD[idx];
        sps[tid] = sparse[idx];
    }
    __syncthreads();

    // Phase A: build h1
    for (int e = tid; e < 64 * DIM; e += 256) {
        const int r = e / DIM;
        const int c = e - r * DIM;
        float v = As[c] + g_B[(d0 + r) * DIM + c];
        v = fmaf(dss[r], wds[c], v);
        v = fmaf(sps[r], wsp[c], v);
        h1s[e] = fmaxf(v, 0.f);
    }
    __syncthreads();

    // Phase B: 64x192 = h1(64x384) @ W2(384x192)
    const int ty = tid >> 4;                 // 0..15 -> 4 rows
    const int tx = tid & 15;                 // 0..15 -> 12 cols
    const int m0 = ty * 4;
    const int n0 = tx * 12;

    float acc[4][12];
#pragma unroll
    for (int i = 0; i < 4; i++)
#pragma unroll
        for (int j = 0; j < 12; j++) acc[i][j] = 0.f;

    for (int k0 = 0; k0 < DIM; k0 += 32) {
        for (int e = tid; e < 32 * H2; e += 256)
            w2s[e] = W2[k0 * H2 + e];
        __syncthreads();

#pragma unroll
        for (int kk = 0; kk < 32; kk += 4) {
            float4 av[4];
#pragma unroll
            for (int i = 0; i < 4; i++)
                av[i] = *(const float4*)(h1s + (m0 + i) * DIM + k0 + kk);
#pragma unroll
            for (int t = 0; t < 4; t++) {
                const float4 v0 = *(const float4*)(w2s + (kk + t) * H2 + n0);
                const float4 v1 = *(const float4*)(w2s + (kk + t) * H2 + n0 + 4);
                const float4 v2 = *(const float4*)(w2s + (kk + t) * H2 + n0 + 8);
                const float bb[12] = {v0.x, v0.y, v0.z, v0.w,
                                      v1.x, v1.y, v1.z, v1.w,
                                      v2.x, v2.y, v2.z, v2.w};
#pragma unroll
                for (int i = 0; i < 4; i++) {
                    const float a = (t == 0) ? av[i].x
                                  : (t == 1) ? av[i].y
                                  : (t == 2) ? av[i].z
                                             : av[i].w;
#pragma unroll
                    for (int j = 0; j < 12; j++)
                        acc[i][j] = fmaf(a, bb[j], acc[i][j]);
                }
            }
        }
        __syncthreads();
    }

    // Layer 3 + sigmoid fusion
    float part[4] = {0.f, 0.f, 0.f, 0.f};
#pragma unroll
    for (int i = 0; i < 4; i++)
#pragma unroll
        for (int j = 0; j < 12; j++) {
            const float h = fmaxf(acc[i][j] + b2s[n0 + j], 0.f);
            part[i] = fmaf(h, w3s[n0 + j], part[i]);
        }

#pragma unroll
    for (int off = 8; off >= 1; off >>= 1) {
#pragma unroll
        for (int i = 0; i < 4; i++)
            part[i] += __shfl_xor_sync(0xffffffffu, part[i], off);
    }

    if (tx == 0) {
        const float bb3 = b3[0];
#pragma unroll
        for (int i = 0; i < 4; i++) {
            const int r = m0 + i;
            const float logit = part[i] + bb3;
            const float w = 1.f / (1.f + expf(-logit));
            out[q * DN + d0 + r] = w * dss[r] + (1.f - w) * sps[r];
        }
    }
}

// ---------------------------------------------------------------------------
extern "C" void kernel_launch(void* const* d_in, const int* in_sizes, int n_in,
                              void* d_out, int out_size)
{
    const float* qd = (const float*)d_in[0];
    const float* dd = (const float*)d_in[1];
    const float* sp = (const float*)d_in[2];
    const float* W1 = (const float*)d_in[3];
    const float* b1 = (const float*)d_in[4];
    const float* W2 = (const float*)d_in[5];
    const float* b2 = (const float*)d_in[6];
    const float* W3 = (const float*)d_in[7];
    const float* b3 = (const float*)d_in[8];
    float* out = (float*)d_out;

    const size_t smem3 = (size_t)(64 * DIM + 32 * H2 + 3 * DIM + 2 * H2 + 128)
                         * sizeof(float);                                    // ~127 KB

    cudaFuncSetAttribute(k_main, cudaFuncAttributeMaxDynamicSharedMemorySize, (int)smem3);

    k_precompute<<<DN / 32 + 1, 256>>>(qd, dd, W1, b1);
    k_dense<<<DN / 64, 256>>>(qd, dd, sp, out);
    k_main<<<(QN * DN) / 64, 256, smem3>>>(W1, W2, b2, W3, b3, sp, out);
}

// round 5
// speedup vs baseline: 1.0228x; 1.0228x over previous
#include <cuda_runtime.h>
#include <math.h>
#include <stdint.h>

#define QN  32
#define DN  4096
#define DIM 384
#define H2  192
#define PADH 388   // h1s row stride (floats): (g*388+tig)%32 unique -> conflict-free A frags
#define PADW 196   // w2s row stride (floats): (tig*196+col)%32 unique -> conflict-free B frags

// Scratch (device globals: allocation-free per harness rules)
__device__ float    g_B[DN * DIM];     // doc_dense @ W1[384:768]
__device__ float    g_A[QN * DIM];     // query_dense @ W1[0:384] + b1
__device__ uint32_t g_W2t[DIM * H2];   // W2 pre-converted to tf32 bit patterns

// ---------------------------------------------------------------------------
__device__ __forceinline__ void mma_tf32(float c[4], const uint32_t a[4],
                                         uint32_t b0, uint32_t b1)
{
    asm volatile(
        "mma.sync.aligned.m16n8k8.row.col.f32.tf32.tf32.f32 "
        "{%0,%1,%2,%3}, {%4,%5,%6,%7}, {%8,%9}, {%0,%1,%2,%3};\n"
        : "+f"(c[0]), "+f"(c[1]), "+f"(c[2]), "+f"(c[3])
        : "r"(a[0]), "r"(a[1]), "r"(a[2]), "r"(a[3]), "r"(b0), "r"(b1));
}

__device__ __forceinline__ uint32_t f32_to_tf32(float v)
{
    uint32_t r;
    asm("cvt.rna.tf32.f32 %0, %1;" : "=r"(r) : "f"(v));
    return r;
}

// ---------------------------------------------------------------------------
// Kernel 0: convert W2 (384x192 f32) to tf32 bits. 72 blocks x 256 thr x 4.
// ---------------------------------------------------------------------------
__global__ void __launch_bounds__(256)
k_cvtw2(const float* __restrict__ W2)
{
    const int i = blockIdx.x * 1024 + threadIdx.x * 4;
    const float4 v = *(const float4*)(W2 + i);
    uint4 o;
    o.x = f32_to_tf32(v.x);
    o.y = f32_to_tf32(v.y);
    o.z = f32_to_tf32(v.z);
    o.w = f32_to_tf32(v.w);
    *(uint4*)(g_W2t + i) = o;
}

// ---------------------------------------------------------------------------
// Kernel 1: precompute A and B (layer-1 factorization GEMMs).
// Blocks 0..511: docs (16 rows, 192-col half each). 512..515: queries.
// Each thread: 1 row x 12 cols. 24KB static smem -> high occupancy.
// ---------------------------------------------------------------------------
__global__ void __launch_bounds__(256)
k_precompute(const float* __restrict__ qd,
             const float* __restrict__ dd,
             const float* __restrict__ W1,
             const float* __restrict__ b1)
{
    __shared__ float Xs[16 * DIM];   // 24 KB
    const int blk = blockIdx.x;
    const int tid = threadIdx.x;

    const float* X;
    const float* Wp;
    float* outp;
    bool isQ;
    int half;
    if (blk < 512) {
        const int rb = blk >> 1;
        half = blk & 1;
        X    = dd + rb * 16 * DIM;
        Wp   = W1 + DIM * DIM;       // W1 rows [384:768]
        outp = g_B + rb * 16 * DIM;
        isQ  = false;
    } else {
        const int qb = blk - 512;
        const int rb = qb >> 1;
        half = qb & 1;
        X    = qd + rb * 16 * DIM;
        Wp   = W1;                   // W1 rows [0:384]
        outp = g_A + rb * 16 * DIM;
        isQ  = true;
    }

    for (int e = tid; e < 16 * DIM; e += 256) Xs[e] = X[e];
    __syncthreads();

    const int row = tid >> 4;                       // 0..15
    const int n0  = half * 192 + (tid & 15) * 12;   // 12 cols

    float acc[12];
#pragma unroll
    for (int j = 0; j < 12; j++) acc[j] = 0.f;

    for (int k = 0; k < DIM; k++) {
        const float a = Xs[row * DIM + k];
        const float4 b0v = *(const float4*)(Wp + k * DIM + n0);
        const float4 b1v = *(const float4*)(Wp + k * DIM + n0 + 4);
        const float4 b2v = *(const float4*)(Wp + k * DIM + n0 + 8);
        acc[0]  = fmaf(a, b0v.x, acc[0]);
        acc[1]  = fmaf(a, b0v.y, acc[1]);
        acc[2]  = fmaf(a, b0v.z, acc[2]);
        acc[3]  = fmaf(a, b0v.w, acc[3]);
        acc[4]  = fmaf(a, b1v.x, acc[4]);
        acc[5]  = fmaf(a, b1v.y, acc[5]);
        acc[6]  = fmaf(a, b1v.z, acc[6]);
        acc[7]  = fmaf(a, b1v.w, acc[7]);
        acc[8]  = fmaf(a, b2v.x, acc[8]);
        acc[9]  = fmaf(a, b2v.y, acc[9]);
        acc[10] = fmaf(a, b2v.z, acc[10]);
        acc[11] = fmaf(a, b2v.w, acc[11]);
    }

#pragma unroll
    for (int j = 0; j < 12; j++) {
        float v = acc[j];
        if (isQ) v += b1[n0 + j];
        outp[row * DIM + n0 + j] = v;
    }
}

// ---------------------------------------------------------------------------
// Kernel 2: dense_scores = query @ doc^T -> out[QN*DN .. 2*QN*DN)
//           sparse copy                  -> out[2*QN*DN .. 3*QN*DN)
// Grid 128: (q-half, 64-doc tile). 16 queries in 24KB static smem.
// ---------------------------------------------------------------------------
__global__ void __launch_bounds__(256)
k_dense(const float* __restrict__ qd,
        const float* __restrict__ dd,
        const float* __restrict__ sparse,
        float* __restrict__ out)
{
    __shared__ float qs[16 * DIM];   // 24 KB

    const int tid = threadIdx.x;
    const int d0  = (blockIdx.x & 63) * 64;
    const int qh  = blockIdx.x >> 6;           // 0 or 1
    const float* qbase = qd + qh * 16 * DIM;

    for (int e = tid; e < 16 * DIM; e += 256) qs[e] = qbase[e];
    __syncthreads();

    const int tx = tid & 63;          // doc within tile
    const int ty = tid >> 6;          // 0..3 -> 4 q's each
    const int d  = d0 + tx;
    const float* drow = dd + d * DIM;

    float acc[4];
#pragma unroll
    for (int i = 0; i < 4; i++) acc[i] = 0.f;

    for (int k = 0; k < DIM; k += 4) {
        const float4 dv4 = *(const float4*)(drow + k);
        const float dv[4] = {dv4.x, dv4.y, dv4.z, dv4.w};
#pragma unroll
        for (int t = 0; t < 4; t++)
#pragma unroll
            for (int i = 0; i < 4; i++)
                acc[i] = fmaf(qs[(ty * 4 + i) * DIM + k + t], dv[t], acc[i]);
    }

    float* outD = out + QN * DN;
    float* outS = out + 2 * QN * DN;
#pragma unroll
    for (int i = 0; i < 4; i++) {
        const int q   = qh * 16 + ty * 4 + i;
        const int idx = q * DN + d;
        outD[idx] = acc[i];
        outS[idx] = sparse[idx];
    }
}

// ---------------------------------------------------------------------------
// Kernel 3: main fused MLP. One CTA = 1 q x 64 docs, 256 threads.
// Phase A: h1[64][384] = relu(A[q]+B[d]+ds*wds+sp*wsp), stored as tf32 bits.
// Phase B: C(64x192) = h1 @ W2 via mma.sync m16n8k8 tf32 (fp32 accum),
//          K staged in 64-row smem tiles. Warp = 2 m-tiles x 6 n-tiles.
// Layer 3: relu + dot(W3) per fragment, shfl over lane-group, smem atomics,
//          sigmoid fusion, store.
// ---------------------------------------------------------------------------
__global__ void __launch_bounds__(256)
k_main(const float* __restrict__ W1,
       const float* __restrict__ b2,
       const float* __restrict__ W3,
       const float* __restrict__ b3,
       const float* __restrict__ sparse,
       float* __restrict__ out)
{
    extern __shared__ float s3[];
    float* h1s    = s3;                       // 64*388 = 24832
    float* w2s    = h1s + 64 * PADH;          // 64*196 = 12544
    float* As     = w2s + 64 * PADW;          // 384
    float* wds    = As  + DIM;                // 384
    float* wsp    = wds + DIM;                // 384
    float* b2s    = wsp + DIM;                // 192
    float* w3s    = b2s + H2;                 // 192
    float* dss    = w3s + H2;                 // 64
    float* sps    = dss + 64;                 // 64
    float* logits = sps + 64;                 // 64

    const int tid = threadIdx.x;
    const int blk = blockIdx.x;
    const int q   = blk >> 6;
    const int d0  = (blk & 63) << 6;
    const float* outD = out + QN * DN;

    for (int e = tid; e < DIM; e += 256) {
        As[e]  = g_A[q * DIM + e];
        wds[e] = W1[768 * DIM + e];
        wsp[e] = W1[769 * DIM + e];
    }
    if (tid < H2) { b2s[tid] = b2[tid]; w3s[tid] = W3[tid]; }
    if (tid < 64) {
        const int idx = q * DN + d0 + tid;
        dss[tid] = outD[idx];
        sps[tid] = sparse[idx];
        logits[tid] = 0.f;
    }
    __syncthreads();

    // Phase A: build h1 (tf32 bits)
    uint32_t* h1w = (uint32_t*)h1s;
    for (int e = tid; e < 64 * DIM; e += 256) {
        const int r = e / DIM;
        const int c = e - r * DIM;
        float v = As[c] + g_B[(d0 + r) * DIM + c];
        v = fmaf(dss[r], wds[c], v);
        v = fmaf(sps[r], wsp[c], v);
        h1w[r * PADH + c] = f32_to_tf32(fmaxf(v, 0.f));
    }
    __syncthreads();

    // Phase B: tensor-core GEMM
    const int lane = tid & 31;
    const int w    = tid >> 5;
    const int g    = lane >> 2;
    const int tig  = lane & 3;
    const int mp   = w & 1;       // row half: rows [mp*32, mp*32+32)
    const int nq   = w >> 1;      // col quarter: cols [nq*48, nq*48+48)

    const uint32_t* h1u = (const uint32_t*)h1s;
    const uint32_t* w2u = (const uint32_t*)w2s;

    float acc[2][6][4];
#pragma unroll
    for (int t = 0; t < 2; t++)
#pragma unroll
        for (int nt = 0; nt < 6; nt++)
#pragma unroll
            for (int i = 0; i < 4; i++) acc[t][nt][i] = 0.f;

    for (int kt = 0; kt < DIM; kt += 64) {
        // stage 64x192 tf32 W2 tile (stride PADW)
        {
            const int r  = tid >> 2;
            const int c0 = (tid & 3) * 48;
            const uint4* src = (const uint4*)(g_W2t + (kt + r) * H2 + c0);
            uint4* dst = (uint4*)(w2s + r * PADW + c0);
#pragma unroll
            for (int j = 0; j < 12; j++) dst[j] = src[j];
        }
        __syncthreads();

#pragma unroll
        for (int kk = 0; kk < 64; kk += 8) {
            uint32_t a[2][4];
#pragma unroll
            for (int t = 0; t < 2; t++) {
                const int base = (mp * 32 + t * 16 + g) * PADH + kt + kk + tig;
                a[t][0] = h1u[base];
                a[t][1] = h1u[base + 8 * PADH];
                a[t][2] = h1u[base + 4];
                a[t][3] = h1u[base + 8 * PADH + 4];
            }
#pragma unroll
            for (int nt = 0; nt < 6; nt++) {
                const int col = nq * 48 + nt * 8 + g;
                const uint32_t b0 = w2u[(kk + tig) * PADW + col];
                const uint32_t b1 = w2u[(kk + tig + 4) * PADW + col];
                mma_tf32(acc[0][nt], a[0], b0, b1);
                mma_tf32(acc[1][nt], a[1], b0, b1);
            }
        }
        __syncthreads();
    }

    // Layer 3: relu + dot W3 on fragments
    // C frag (16x8): c0=(g,2tig) c1=(g,2tig+1) c2=(g+8,2tig) c3=(g+8,2tig+1)
    float p[2][2] = {{0.f, 0.f}, {0.f, 0.f}};
#pragma unroll
    for (int t = 0; t < 2; t++)
#pragma unroll
        for (int nt = 0; nt < 6; nt++) {
            const int col = nq * 48 + nt * 8 + 2 * tig;
            float h;
            h = fmaxf(acc[t][nt][0] + b2s[col],     0.f); p[t][0] = fmaf(h, w3s[col],     p[t][0]);
            h = fmaxf(acc[t][nt][1] + b2s[col + 1], 0.f); p[t][0] = fmaf(h, w3s[col + 1], p[t][0]);
            h = fmaxf(acc[t][nt][2] + b2s[col],     0.f); p[t][1] = fmaf(h, w3s[col],     p[t][1]);
            h = fmaxf(acc[t][nt][3] + b2s[col + 1], 0.f); p[t][1] = fmaf(h, w3s[col + 1], p[t][1]);
        }

#pragma unroll
    for (int t = 0; t < 2; t++)
#pragma unroll
        for (int hseg = 0; hseg < 2; hseg++) {
            p[t][hseg] += __shfl_xor_sync(0xffffffffu, p[t][hseg], 1);
            p[t][hseg] += __shfl_xor_sync(0xffffffffu, p[t][hseg], 2);
        }

    if (tig == 0) {
#pragma unroll
        for (int t = 0; t < 2; t++) {
            atomicAdd(&logits[mp * 32 + t * 16 + g],     p[t][0]);
            atomicAdd(&logits[mp * 32 + t * 16 + g + 8], p[t][1]);
        }
    }
    __syncthreads();

    if (tid < 64) {
        const float logit = logits[tid] + b3[0];
        const float wgt   = 1.f / (1.f + expf(-logit));
        out[q * DN + d0 + tid] = wgt * dss[tid] + (1.f - wgt) * sps[tid];
    }
}

// ---------------------------------------------------------------------------
extern "C" void kernel_launch(void* const* d_in, const int* in_sizes, int n_in,
                              void* d_out, int out_size)
{
    const float* qd = (const float*)d_in[0];
    const float* dd = (const float*)d_in[1];
    const float* sp = (const float*)d_in[2];
    const float* W1 = (const float*)d_in[3];
    const float* b1 = (const float*)d_in[4];
    const float* W2 = (const float*)d_in[5];
    const float* b2 = (const float*)d_in[6];
    const float* W3 = (const float*)d_in[7];
    const float* b3 = (const float*)d_in[8];
    float* out = (float*)d_out;

    // k_main smem: 64*388 + 64*196 + 3*384 + 2*192 + 3*64 floats
    const size_t smem3 = (size_t)(64 * PADH + 64 * PADW + 3 * DIM + 2 * H2 + 3 * 64)
                         * sizeof(float);   // 156,416 B

    cudaFuncSetAttribute(k_main, cudaFuncAttributeMaxDynamicSharedMemorySize, (int)smem3);

    k_cvtw2<<<(DIM * H2) / 1024, 256>>>(W2);
    k_precompute<<<516, 256>>>(qd, dd, W1, b1);
    k_dense<<<128, 256>>>(qd, dd, sp, out);
    k_main<<<(QN * DN) / 64, 256, smem3>>>(W1, b2, W3, b3, sp, out);
}

// round 8
// speedup vs baseline: 2.0459x; 2.0002x over previous
#include <cuda_runtime.h>
#include <math.h>
#include <stdint.h>

#define QN  32
#define DN  4096
#define DIM 384
#define H2  192
#define KC    32          // K chunk
#define NCH   12          // DIM / KC
#define PADHC 36          // h1 chunk row stride (floats) -> conflict-free A frags
#define PADW  196         // w2 tile row stride (floats)  -> conflict-free B frags

// Scratch (device globals: allocation-free per harness rules)
__device__ float    g_B[DN * DIM];     // doc_dense @ W1[384:768]
__device__ float    g_A[QN * DIM];     // query_dense @ W1[0:384] + b1
__device__ uint32_t g_W2t[DIM * H2];   // W2 pre-converted to tf32 bit patterns

// ---------------------------------------------------------------------------
__device__ __forceinline__ void mma_tf32(float c[4], const uint32_t a[4],
                                         uint32_t b0, uint32_t b1)
{
    asm volatile(
        "mma.sync.aligned.m16n8k8.row.col.f32.tf32.tf32.f32 "
        "{%0,%1,%2,%3}, {%4,%5,%6,%7}, {%8,%9}, {%0,%1,%2,%3};\n"
        : "+f"(c[0]), "+f"(c[1]), "+f"(c[2]), "+f"(c[3])
        : "r"(a[0]), "r"(a[1]), "r"(a[2]), "r"(a[3]), "r"(b0), "r"(b1));
}

__device__ __forceinline__ uint32_t f32_to_tf32(float v)
{
    uint32_t r;
    asm("cvt.rna.tf32.f32 %0, %1;" : "=r"(r) : "f"(v));
    return r;
}

__device__ __forceinline__ void cp_async16(uint32_t dst_smem, const void* src)
{
    asm volatile("cp.async.cg.shared.global [%0], [%1], 16;\n"
                 :: "r"(dst_smem), "l"(src));
}
#define CP_COMMIT() asm volatile("cp.async.commit_group;\n" ::: "memory")
#define CP_WAIT0()  asm volatile("cp.async.wait_group 0;\n" ::: "memory")

// ---------------------------------------------------------------------------
// Kernel 0: convert W2 (384x192 f32) to tf32 bits.
// ---------------------------------------------------------------------------
__global__ void __launch_bounds__(256)
k_cvtw2(const float* __restrict__ W2)
{
    const int i = blockIdx.x * 1024 + threadIdx.x * 4;
    const float4 v = *(const float4*)(W2 + i);
    uint4 o;
    o.x = f32_to_tf32(v.x);
    o.y = f32_to_tf32(v.y);
    o.z = f32_to_tf32(v.z);
    o.w = f32_to_tf32(v.w);
    *(uint4*)(g_W2t + i) = o;
}

// ---------------------------------------------------------------------------
// Kernel 1: precompute A and B (layer-1 factorization GEMMs).
// Blocks 0..511: docs (16 rows, 192-col half each). 512..515: queries.
// ---------------------------------------------------------------------------
__global__ void __launch_bounds__(256)
k_precompute(const float* __restrict__ qd,
             const float* __restrict__ dd,
             const float* __restrict__ W1,
             const float* __restrict__ b1)
{
    __shared__ float Xs[16 * DIM];   // 24 KB
    const int blk = blockIdx.x;
    const int tid = threadIdx.x;

    const float* X;
    const float* Wp;
    float* outp;
    bool isQ;
    int half;
    if (blk < 512) {
        const int rb = blk >> 1;
        half = blk & 1;
        X    = dd + rb * 16 * DIM;
        Wp   = W1 + DIM * DIM;       // W1 rows [384:768]
        outp = g_B + rb * 16 * DIM;
        isQ  = false;
    } else {
        const int qb = blk - 512;
        const int rb = qb >> 1;
        half = qb & 1;
        X    = qd + rb * 16 * DIM;
        Wp   = W1;                   // W1 rows [0:384]
        outp = g_A + rb * 16 * DIM;
        isQ  = true;
    }

    for (int e = tid; e < 16 * DIM; e += 256) Xs[e] = X[e];
    __syncthreads();

    const int row = tid >> 4;                       // 0..15
    const int n0  = half * 192 + (tid & 15) * 12;   // 12 cols

    float acc[12];
#pragma unroll
    for (int j = 0; j < 12; j++) acc[j] = 0.f;

#pragma unroll 4
    for (int k = 0; k < DIM; k++) {
        const float a = Xs[row * DIM + k];
        const float4 b0v = *(const float4*)(Wp + k * DIM + n0);
        const float4 b1v = *(const float4*)(Wp + k * DIM + n0 + 4);
        const float4 b2v = *(const float4*)(Wp + k * DIM + n0 + 8);
        acc[0]  = fmaf(a, b0v.x, acc[0]);
        acc[1]  = fmaf(a, b0v.y, acc[1]);
        acc[2]  = fmaf(a, b0v.z, acc[2]);
        acc[3]  = fmaf(a, b0v.w, acc[3]);
        acc[4]  = fmaf(a, b1v.x, acc[4]);
        acc[5]  = fmaf(a, b1v.y, acc[5]);
        acc[6]  = fmaf(a, b1v.z, acc[6]);
        acc[7]  = fmaf(a, b1v.w, acc[7]);
        acc[8]  = fmaf(a, b2v.x, acc[8]);
        acc[9]  = fmaf(a, b2v.y, acc[9]);
        acc[10] = fmaf(a, b2v.z, acc[10]);
        acc[11] = fmaf(a, b2v.w, acc[11]);
    }

#pragma unroll
    for (int j = 0; j < 12; j++) {
        float v = acc[j];
        if (isQ) v += b1[n0 + j];
        outp[row * DIM + n0 + j] = v;
    }
}

// ---------------------------------------------------------------------------
// Kernel 2: dense_scores + sparse copy.
// ---------------------------------------------------------------------------
__global__ void __launch_bounds__(256)
k_dense(const float* __restrict__ qd,
        const float* __restrict__ dd,
        const float* __restrict__ sparse,
        float* __restrict__ out)
{
    __shared__ float qs[16 * DIM];   // 24 KB

    const int tid = threadIdx.x;
    const int d0  = (blockIdx.x & 63) * 64;
    const int qh  = blockIdx.x >> 6;           // 0 or 1
    const float* qbase = qd + qh * 16 * DIM;

    for (int e = tid; e < 16 * DIM; e += 256) qs[e] = qbase[e];
    __syncthreads();

    const int tx = tid & 63;
    const int ty = tid >> 6;          // 0..3 -> 4 q's each
    const int d  = d0 + tx;
    const float* drow = dd + d * DIM;

    float acc[4];
#pragma unroll
    for (int i = 0; i < 4; i++) acc[i] = 0.f;

    for (int k = 0; k < DIM; k += 4) {
        const float4 dv4 = *(const float4*)(drow + k);
        const float dv[4] = {dv4.x, dv4.y, dv4.z, dv4.w};
#pragma unroll
        for (int t = 0; t < 4; t++)
#pragma unroll
            for (int i = 0; i < 4; i++)
                acc[i] = fmaf(qs[(ty * 4 + i) * DIM + k + t], dv[t], acc[i]);
    }

    float* outD = out + QN * DN;
    float* outS = out + 2 * QN * DN;
#pragma unroll
    for (int i = 0; i < 4; i++) {
        const int q   = qh * 16 + ty * 4 + i;
        const int idx = q * DN + d;
        outD[idx] = acc[i];
        outS[idx] = sparse[idx];
    }
}

// ---------------------------------------------------------------------------
// Kernel 3: main fused MLP. One CTA = 1 q x 64 docs, 256 threads, 66KB smem
// -> 3 CTAs/SM. K chunked (KC=32): h1 chunk built from register-prefetched
// g_B; W2 tiles double-buffered via cp.async. tf32 mma.sync m16n8k8.
// ---------------------------------------------------------------------------
__global__ void __launch_bounds__(256, 3)
k_main(const float* __restrict__ W1,
       const float* __restrict__ b2,
       const float* __restrict__ W3,
       const float* __restrict__ b3,
       const float* __restrict__ sparse,
       float* __restrict__ out)
{
    extern __shared__ float s3[];
    float* hbuf   = s3;                         // 64*36  = 2304
    float* wbuf   = hbuf + 64 * PADHC;          // 2*32*196 = 12544
    float* As     = wbuf + 2 * KC * PADW;       // 384
    float* wds    = As  + DIM;                  // 384
    float* wsp    = wds + DIM;                  // 384
    float* b2s    = wsp + DIM;                  // 192
    float* w3s    = b2s + H2;                   // 192
    float* dss    = w3s + H2;                   // 64
    float* sps    = dss + 64;                   // 64
    float* logits = sps + 64;                   // 64

    uint32_t smem_u32;
    asm("{ .reg .u64 t; cvta.to.shared.u64 t, %1; cvt.u32.u64 %0, t; }"
        : "=r"(smem_u32) : "l"(s3));
    const uint32_t wbuf_u32 = smem_u32 + 64 * PADHC * 4;

    const int tid = threadIdx.x;
    const int blk = blockIdx.x;
    const int q   = blk >> 6;
    const int d0  = (blk & 63) << 6;
    const float* outD = out + QN * DN;

    for (int e = tid; e < DIM; e += 256) {
        As[e]  = g_A[q * DIM + e];
        wds[e] = W1[768 * DIM + e];
        wsp[e] = W1[769 * DIM + e];
    }
    if (tid < H2) { b2s[tid] = b2[tid]; w3s[tid] = W3[tid]; }
    if (tid < 64) {
        const int idx = q * DN + d0 + tid;
        dss[tid] = outD[idx];
        sps[tid] = sparse[idx];
        logits[tid] = 0.f;
    }
    __syncthreads();

    // ---- per-thread Phase-A indexing (row r, 8-col group) ----
    const int ar  = tid >> 2;               // 0..63 doc row
    const int acg = (tid & 3) * 8;          // col group within chunk
    const float rds = dss[ar];
    const float rsp = sps[ar];
    const float* gbrow = g_B + (size_t)(d0 + ar) * DIM + acg;
    uint4* hdst = (uint4*)(hbuf + ar * PADHC + acg);

    // ---- W2 cp.async indexing ----
    const int wr = tid >> 3;                // 0..31 k-row in tile
    const int wc = (tid & 7) * 24;          // 24 cols
    const uint32_t wdst0 = wbuf_u32 + (uint32_t)(wr * PADW + wc) * 4;

    // ---- MMA warp layout ----
    const int lane = tid & 31;
    const int w    = tid >> 5;
    const int g    = lane >> 2;
    const int tig  = lane & 3;
    const int mp   = w & 1;                 // row half (32 rows)
    const int nq   = w >> 1;                // 48-col quarter

    float acc[2][6][4];
#pragma unroll
    for (int t = 0; t < 2; t++)
#pragma unroll
        for (int nt = 0; nt < 6; nt++)
#pragma unroll
            for (int i = 0; i < 4; i++) acc[t][nt][i] = 0.f;

    // ---- prologue: stage chunk 0 ----
    {
        const uint32_t* src = g_W2t + wr * H2 + wc;
#pragma unroll
        for (int i = 0; i < 6; i++) cp_async16(wdst0 + i * 16, src + i * 4);
        CP_COMMIT();

        const float4 va = *(const float4*)(gbrow);
        const float4 vb = *(const float4*)(gbrow + 4);
        const float v[8] = {va.x, va.y, va.z, va.w, vb.x, vb.y, vb.z, vb.w};
        uint32_t o[8];
#pragma unroll
        for (int j = 0; j < 8; j++) {
            float x = As[acg + j] + v[j];
            x = fmaf(rds, wds[acg + j], x);
            x = fmaf(rsp, wsp[acg + j], x);
            o[j] = f32_to_tf32(fmaxf(x, 0.f));
        }
        hdst[0] = make_uint4(o[0], o[1], o[2], o[3]);
        hdst[1] = make_uint4(o[4], o[5], o[6], o[7]);
        CP_WAIT0();
    }
    __syncthreads();

    const uint32_t* h1u = (const uint32_t*)hbuf;

    for (int c = 0; c < NCH; c++) {
        const int p = c & 1;

        // prefetch chunk c+1
        float4 va, vb;
        if (c < NCH - 1) {
            const int ktn = (c + 1) * KC;
            const uint32_t* src = g_W2t + (ktn + wr) * H2 + wc;
            const uint32_t wdst = wdst0 + (uint32_t)((1 - p) * KC * PADW) * 4;
#pragma unroll
            for (int i = 0; i < 6; i++) cp_async16(wdst + i * 16, src + i * 4);
            CP_COMMIT();
            va = *(const float4*)(gbrow + ktn);
            vb = *(const float4*)(gbrow + ktn + 4);
        }

        // MMA on chunk c
        const uint32_t* w2u = (const uint32_t*)(wbuf + p * KC * PADW);
#pragma unroll
        for (int kk = 0; kk < KC; kk += 8) {
            uint32_t a[2][4];
#pragma unroll
            for (int t = 0; t < 2; t++) {
                const int base = (mp * 32 + t * 16 + g) * PADHC + kk + tig;
                a[t][0] = h1u[base];
                a[t][1] = h1u[base + 8 * PADHC];
                a[t][2] = h1u[base + 4];
                a[t][3] = h1u[base + 8 * PADHC + 4];
            }
#pragma unroll
            for (int nt = 0; nt < 6; nt++) {
                const int col = nq * 48 + nt * 8 + g;
                const uint32_t b0 = w2u[(kk + tig) * PADW + col];
                const uint32_t b1 = w2u[(kk + tig + 4) * PADW + col];
                mma_tf32(acc[0][nt], a[0], b0, b1);
                mma_tf32(acc[1][nt], a[1], b0, b1);
            }
        }
        CP_WAIT0();
        __syncthreads();   // MMA done (hbuf free) + next W2 visible

        if (c < NCH - 1) {
            const int ktn = (c + 1) * KC;
            const float v[8] = {va.x, va.y, va.z, va.w, vb.x, vb.y, vb.z, vb.w};
            uint32_t o[8];
#pragma unroll
            for (int j = 0; j < 8; j++) {
                const int col = ktn + acg + j;
                float x = As[col] + v[j];
                x = fmaf(rds, wds[col], x);
                x = fmaf(rsp, wsp[col], x);
                o[j] = f32_to_tf32(fmaxf(x, 0.f));
            }
            hdst[0] = make_uint4(o[0], o[1], o[2], o[3]);
            hdst[1] = make_uint4(o[4], o[5], o[6], o[7]);
            __syncthreads();  // publish h1 chunk c+1
        }
    }

    // Layer 3: relu + dot W3 on fragments
    float pr[2][2] = {{0.f, 0.f}, {0.f, 0.f}};
#pragma unroll
    for (int t = 0; t < 2; t++)
#pragma unroll
        for (int nt = 0; nt < 6; nt++) {
            const int col = nq * 48 + nt * 8 + 2 * tig;
            float h;
            h = fmaxf(acc[t][nt][0] + b2s[col],     0.f); pr[t][0] = fmaf(h, w3s[col],     pr[t][0]);
            h = fmaxf(acc[t][nt][1] + b2s[col + 1], 0.f); pr[t][0] = fmaf(h, w3s[col + 1], pr[t][0]);
            h = fmaxf(acc[t][nt][2] + b2s[col],     0.f); pr[t][1] = fmaf(h, w3s[col],     pr[t][1]);
            h = fmaxf(acc[t][nt][3] + b2s[col + 1], 0.f); pr[t][1] = fmaf(h, w3s[col + 1], pr[t][1]);
        }

#pragma unroll
    for (int t = 0; t < 2; t++)
#pragma unroll
        for (int hseg = 0; hseg < 2; hseg++) {
            pr[t][hseg] += __shfl_xor_sync(0xffffffffu, pr[t][hseg], 1);
            pr[t][hseg] += __shfl_xor_sync(0xffffffffu, pr[t][hseg], 2);
        }

    if (tig == 0) {
#pragma unroll
        for (int t = 0; t < 2; t++) {
            atomicAdd(&logits[mp * 32 + t * 16 + g],     pr[t][0]);
            atomicAdd(&logits[mp * 32 + t * 16 + g + 8], pr[t][1]);
        }
    }
    __syncthreads();

    if (tid < 64) {
        const float logit = logits[tid] + b3[0];
        const float wgt   = 1.f / (1.f + expf(-logit));
        out[q * DN + d0 + tid] = wgt * dss[tid] + (1.f - wgt) * sps[tid];
    }
}

// ---------------------------------------------------------------------------
extern "C" void kernel_launch(void* const* d_in, const int* in_sizes, int n_in,
                              void* d_out, int out_size)
{
    const float* qd = (const float*)d_in[0];
    const float* dd = (const float*)d_in[1];
    const float* sp = (const float*)d_in[2];
    const float* W1 = (const float*)d_in[3];
    const float* b1 = (const float*)d_in[4];
    const float* W2 = (const float*)d_in[5];
    const float* b2 = (const float*)d_in[6];
    const float* W3 = (const float*)d_in[7];
    const float* b3 = (const float*)d_in[8];
    float* out = (float*)d_out;

    const size_t smem3 = (size_t)(64 * PADHC + 2 * KC * PADW + 3 * DIM
                                  + 2 * H2 + 3 * 64) * sizeof(float); // 66304 B

    cudaFuncSetAttribute(k_main, cudaFuncAttributeMaxDynamicSharedMemorySize, (int)smem3);

    k_cvtw2<<<(DIM * H2) / 1024, 256>>>(W2);
    k_precompute<<<516, 256>>>(qd, dd, W1, b1);
    k_dense<<<128, 256>>>(qd, dd, sp, out);
    k_main<<<(QN * DN) / 64, 256, smem3>>>(W1, b2, W3, b3, sp, out);
}

// round 9
// speedup vs baseline: 3.6096x; 1.7643x over previous
#include <cuda_runtime.h>
#include <math.h>
#include <stdint.h>

#define QN  32
#define DN  4096
#define DIM 384
#define H2  192
#define KC    32          // K chunk (16 bf16 pairs)
#define NCH   12          // DIM / KC
#define HP    20          // hbuf row stride (u32 pairs): 16 + 4 pad, conflict-free
#define WP    200         // w2 pair-row stride (u32): 192 + 8 pad, conflict-free
#define GS    36          // gbstage row stride (floats): 32 + 4 pad

// Scratch (device globals: allocation-free per harness rules)
__device__ float    g_B[DN * DIM];     // doc_dense @ W1[384:768]
__device__ float    g_A[QN * DIM];     // query_dense @ W1[0:384] + b1
__device__ uint32_t g_W2p[(DIM / 2) * H2];  // W2 packed bf16x2 along K: [pair][n]

// ---------------------------------------------------------------------------
__device__ __forceinline__ uint32_t pack_bf16x2(float lo, float hi)
{
    uint32_t r;
    asm("cvt.rn.bf16x2.f32 %0, %1, %2;" : "=r"(r) : "f"(hi), "f"(lo));
    return r;
}

__device__ __forceinline__ void mma_bf16(float c[4], const uint32_t a[4],
                                         uint32_t b0, uint32_t b1)
{
    asm volatile(
        "mma.sync.aligned.m16n8k16.row.col.f32.bf16.bf16.f32 "
        "{%0,%1,%2,%3}, {%4,%5,%6,%7}, {%8,%9}, {%0,%1,%2,%3};\n"
        : "+f"(c[0]), "+f"(c[1]), "+f"(c[2]), "+f"(c[3])
        : "r"(a[0]), "r"(a[1]), "r"(a[2]), "r"(a[3]), "r"(b0), "r"(b1));
}

__device__ __forceinline__ void cp_async16(uint32_t dst_smem, const void* src)
{
    asm volatile("cp.async.cg.shared.global [%0], [%1], 16;\n"
                 :: "r"(dst_smem), "l"(src));
}
#define CP_COMMIT() asm volatile("cp.async.commit_group;\n" ::: "memory")
#define CP_WAIT0()  asm volatile("cp.async.wait_group 0;\n" ::: "memory")

// ---------------------------------------------------------------------------
// Kernel 0: pack W2 (384x192 f32) into bf16x2 pairs along K.
// g_W2p[p*192+n] = {lo=W2[2p][n], hi=W2[2p+1][n]}
// ---------------------------------------------------------------------------
__global__ void __launch_bounds__(192)
k_cvtw2p(const float* __restrict__ W2)
{
    const int p = blockIdx.x;    // 0..191
    const int n = threadIdx.x;   // 0..191
    g_W2p[p * H2 + n] = pack_bf16x2(W2[(2 * p) * H2 + n],
                                    W2[(2 * p + 1) * H2 + n]);
}

// ---------------------------------------------------------------------------
// Kernel 1: precompute A and B (layer-1 factorization GEMMs).
// Blocks 0..255: docs (32 rows, 192-col half each). 256..257: queries.
// Each thread: 2 rows x 12 cols.
// ---------------------------------------------------------------------------
__global__ void __launch_bounds__(256)
k_precompute(const float* __restrict__ qd,
             const float* __restrict__ dd,
             const float* __restrict__ W1,
             const float* __restrict__ b1)
{
    __shared__ float Xs[32 * DIM];   // 48 KB
    const int blk = blockIdx.x;
    const int tid = threadIdx.x;

    const float* X;
    const float* Wp;
    float* outp;
    bool isQ;
    int half;
    if (blk < 256) {
        const int rb = blk >> 1;
        half = blk & 1;
        X    = dd + rb * 32 * DIM;
        Wp   = W1 + DIM * DIM;       // W1 rows [384:768]
        outp = g_B + rb * 32 * DIM;
        isQ  = false;
    } else {
        half = blk - 256;
        X    = qd;
        Wp   = W1;                   // W1 rows [0:384]
        outp = g_A;
        isQ  = true;
    }

    for (int e = tid; e < 32 * DIM; e += 256) Xs[e] = X[e];
    __syncthreads();

    const int r0 = (tid >> 4) * 2;                  // rows r0, r0+1
    const int n0 = half * 192 + (tid & 15) * 12;    // 12 cols

    float acc[2][12];
#pragma unroll
    for (int i = 0; i < 2; i++)
#pragma unroll
        for (int j = 0; j < 12; j++) acc[i][j] = 0.f;

#pragma unroll 4
    for (int k = 0; k < DIM; k++) {
        const float a0 = Xs[r0 * DIM + k];
        const float a1 = Xs[(r0 + 1) * DIM + k];
        const float4 w0 = *(const float4*)(Wp + k * DIM + n0);
        const float4 w1 = *(const float4*)(Wp + k * DIM + n0 + 4);
        const float4 w2 = *(const float4*)(Wp + k * DIM + n0 + 8);
        const float ww[12] = {w0.x, w0.y, w0.z, w0.w,
                              w1.x, w1.y, w1.z, w1.w,
                              w2.x, w2.y, w2.z, w2.w};
#pragma unroll
        for (int j = 0; j < 12; j++) {
            acc[0][j] = fmaf(a0, ww[j], acc[0][j]);
            acc[1][j] = fmaf(a1, ww[j], acc[1][j]);
        }
    }

#pragma unroll
    for (int i = 0; i < 2; i++)
#pragma unroll
        for (int j = 0; j < 12; j++) {
            float v = acc[i][j];
            if (isQ) v += b1[n0 + j];
            outp[(r0 + i) * DIM + n0 + j] = v;
        }
}

// ---------------------------------------------------------------------------
// Kernel 2: dense_scores + sparse copy.
// ---------------------------------------------------------------------------
__global__ void __launch_bounds__(256)
k_dense(const float* __restrict__ qd,
        const float* __restrict__ dd,
        const float* __restrict__ sparse,
        float* __restrict__ out)
{
    __shared__ float qs[16 * DIM];   // 24 KB

    const int tid = threadIdx.x;
    const int d0  = (blockIdx.x & 63) * 64;
    const int qh  = blockIdx.x >> 6;           // 0 or 1
    const float* qbase = qd + qh * 16 * DIM;

    for (int e = tid; e < 16 * DIM; e += 256) qs[e] = qbase[e];
    __syncthreads();

    const int tx = tid & 63;
    const int ty = tid >> 6;          // 0..3 -> 4 q's each
    const int d  = d0 + tx;
    const float* drow = dd + d * DIM;

    float acc[4];
#pragma unroll
    for (int i = 0; i < 4; i++) acc[i] = 0.f;

    for (int k = 0; k < DIM; k += 4) {
        const float4 dv4 = *(const float4*)(drow + k);
        const float dv[4] = {dv4.x, dv4.y, dv4.z, dv4.w};
#pragma unroll
        for (int t = 0; t < 4; t++)
#pragma unroll
            for (int i = 0; i < 4; i++)
                acc[i] = fmaf(qs[(ty * 4 + i) * DIM + k + t], dv[t], acc[i]);
    }

    float* outD = out + QN * DN;
    float* outS = out + 2 * QN * DN;
#pragma unroll
    for (int i = 0; i < 4; i++) {
        const int q   = qh * 16 + ty * 4 + i;
        const int idx = q * DN + d;
        outD[idx] = acc[i];
        outS[idx] = sparse[idx];
    }
}

// ---------------------------------------------------------------------------
// Kernel 3: main fused MLP. One CTA = 1 q x 64 docs, 256 threads, ~60KB smem
// -> 3 CTAs/SM. bf16 mma m16n8k16. hbuf double-buffered, W2 + g_B staged via
// cp.async (double-buffered) -> ONE barrier per K chunk.
// ---------------------------------------------------------------------------
__global__ void __launch_bounds__(256, 3)
k_main(const float* __restrict__ W1,
       const float* __restrict__ b2,
       const float* __restrict__ W3,
       const float* __restrict__ b3,
       const float* __restrict__ sparse,
       float* __restrict__ out)
{
    extern __shared__ float s3[];
    uint32_t* hbufu = (uint32_t*)s3;            // 2 * 64*HP   = 2560 u32
    uint32_t* wbufu = hbufu + 2 * 64 * HP;      // 2 * 16*WP   = 6400 u32
    float* gbst     = (float*)(wbufu + 2 * 16 * WP);  // 2 * 64*GS = 4608 f
    float* As       = gbst + 2 * 64 * GS;       // 384
    float* wds      = As  + DIM;                // 384
    float* wsp      = wds + DIM;                // 384
    float* b2s      = wsp + DIM;                // 192
    float* w3s      = b2s + H2;                 // 192
    float* dss      = w3s + H2;                 // 64
    float* sps      = dss + 64;                 // 64
    float* logits   = sps + 64;                 // 64

    uint32_t smem_u32;
    asm("{ .reg .u64 t; cvta.to.shared.u64 t, %1; cvt.u32.u64 %0, t; }"
        : "=r"(smem_u32) : "l"(s3));
    const uint32_t wbuf_b = smem_u32 + (2 * 64 * HP) * 4;
    const uint32_t gbst_b = smem_u32 + (2 * 64 * HP + 2 * 16 * WP) * 4;

    const int tid = threadIdx.x;
    const int blk = blockIdx.x;
    const int q   = blk >> 6;
    const int d0  = (blk & 63) << 6;
    const float* outD = out + QN * DN;

    for (int e = tid; e < DIM; e += 256) {
        As[e]  = g_A[q * DIM + e];
        wds[e] = W1[768 * DIM + e];
        wsp[e] = W1[769 * DIM + e];
    }
    if (tid < H2) { b2s[tid] = b2[tid]; w3s[tid] = W3[tid]; }
    if (tid < 64) {
        const int idx = q * DN + d0 + tid;
        dss[tid] = outD[idx];
        sps[tid] = sparse[idx];
        logits[tid] = 0.f;
    }
    __syncthreads();

    // ---- per-thread Phase-A indexing ----
    const int ar  = tid >> 2;               // 0..63 doc row
    const int acw = tid & 3;                // col quarter (8 cols / 4 pairs)
    const float rds = dss[ar];
    const float rsp = sps[ar];

    // ---- cp.async indexing ----
    const int wr = tid >> 4;                // 0..15 W2 pair-row
    const int wc = (tid & 15) * 12;         // 12 u32 = 48B -> 3 cp16
    const int gr = tid >> 2;                // 0..63 g_B row
    const int gc = (tid & 3) * 8;           // 8 floats = 32B -> 2 cp16
    const float* gB_base = g_B + (size_t)(d0 + gr) * DIM + gc;

    // ---- MMA warp layout ----
    const int lane = tid & 31;
    const int w    = tid >> 5;
    const int g    = lane >> 2;
    const int tig  = lane & 3;
    const int mp   = w & 1;                 // row half (32 rows)
    const int nq   = w >> 1;                // 48-col quarter

    float acc[2][6][4];
#pragma unroll
    for (int t = 0; t < 2; t++)
#pragma unroll
        for (int nt = 0; nt < 6; nt++)
#pragma unroll
            for (int i = 0; i < 4; i++) acc[t][nt][i] = 0.f;

    // ---- prologue: issue cp group {W2(0)->wbuf0, gB(1)->gbst1}, build h0 ----
    {
        const uint32_t* srcw = g_W2p + wr * H2 + wc;      // chunk 0 pairs
        const uint32_t wdst = wbuf_b + (uint32_t)(wr * WP + wc) * 4;
#pragma unroll
        for (int i = 0; i < 3; i++) cp_async16(wdst + i * 16, srcw + i * 4);
        const float* srcg = gB_base + KC;                 // chunk 1 cols
        const uint32_t gdst = gbst_b + (uint32_t)(64 * GS + gr * GS + gc) * 4;
        cp_async16(gdst,      srcg);
        cp_async16(gdst + 16, srcg + 4);
        CP_COMMIT();

        // build h chunk 0 from g_B directly (LDG)
        const float* gb = g_B + (size_t)(d0 + ar) * DIM + acw * 8;
        const float4 va = *(const float4*)gb;
        const float4 vb = *(const float4*)(gb + 4);
        const int col0 = acw * 8;
        const float4 A0 = *(const float4*)(As + col0);
        const float4 A1 = *(const float4*)(As + col0 + 4);
        const float4 D0 = *(const float4*)(wds + col0);
        const float4 D1 = *(const float4*)(wds + col0 + 4);
        const float4 S0 = *(const float4*)(wsp + col0);
        const float4 S1 = *(const float4*)(wsp + col0 + 4);
        const float v[8] = {va.x, va.y, va.z, va.w, vb.x, vb.y, vb.z, vb.w};
        const float a[8] = {A0.x, A0.y, A0.z, A0.w, A1.x, A1.y, A1.z, A1.w};
        const float dw[8] = {D0.x, D0.y, D0.z, D0.w, D1.x, D1.y, D1.z, D1.w};
        const float sw[8] = {S0.x, S0.y, S0.z, S0.w, S1.x, S1.y, S1.z, S1.w};
        float x[8];
#pragma unroll
        for (int j = 0; j < 8; j++) {
            float t0 = a[j] + v[j];
            t0 = fmaf(rds, dw[j], t0);
            t0 = fmaf(rsp, sw[j], t0);
            x[j] = fmaxf(t0, 0.f);
        }
        uint4 o = make_uint4(pack_bf16x2(x[0], x[1]), pack_bf16x2(x[2], x[3]),
                             pack_bf16x2(x[4], x[5]), pack_bf16x2(x[6], x[7]));
        *(uint4*)(hbufu + ar * HP + acw * 4) = o;
    }

    for (int c = 0; c < NCH; c++) {
        CP_WAIT0();
        __syncthreads();   // prev cp visible + all builds/MMAs of prev iter done

        // issue cp for W2(c+1) and gB(c+2)
        if (c < NCH - 1) {
            const int pr = (c + 1) * (KC / 2);   // pair base of chunk c+1
            const uint32_t* srcw = g_W2p + (pr + wr) * H2 + wc;
            const uint32_t wdst = wbuf_b
                + (uint32_t)(((c + 1) & 1) * 16 * WP + wr * WP + wc) * 4;
#pragma unroll
            for (int i = 0; i < 3; i++) cp_async16(wdst + i * 16, srcw + i * 4);
            if (c < NCH - 2) {
                const float* srcg = gB_base + (c + 2) * KC;
                const uint32_t gdst = gbst_b
                    + (uint32_t)(((c + 2) & 1) * 64 * GS + gr * GS + gc) * 4;
                cp_async16(gdst,      srcg);
                cp_async16(gdst + 16, srcg + 4);
            }
            CP_COMMIT();
        }

        // build h chunk c+1 into hbuf[(c+1)&1] from gbst[(c+1)&1]
        if (c < NCH - 1) {
            const float* gs = gbst + ((c + 1) & 1) * 64 * GS + ar * GS + acw * 8;
            const float4 va = ((const float4*)gs)[0];
            const float4 vb = ((const float4*)gs)[1];
            const int col0 = (c + 1) * KC + acw * 8;
            const float4 A0 = *(const float4*)(As + col0);
            const float4 A1 = *(const float4*)(As + col0 + 4);
            const float4 D0 = *(const float4*)(wds + col0);
            const float4 D1 = *(const float4*)(wds + col0 + 4);
            const float4 S0 = *(const float4*)(wsp + col0);
            const float4 S1 = *(const float4*)(wsp + col0 + 4);
            const float v[8] = {va.x, va.y, va.z, va.w, vb.x, vb.y, vb.z, vb.w};
            const float a[8] = {A0.x, A0.y, A0.z, A0.w, A1.x, A1.y, A1.z, A1.w};
            const float dw[8] = {D0.x, D0.y, D0.z, D0.w, D1.x, D1.y, D1.z, D1.w};
            const float sw[8] = {S0.x, S0.y, S0.z, S0.w, S1.x, S1.y, S1.z, S1.w};
            float x[8];
#pragma unroll
            for (int j = 0; j < 8; j++) {
                float t0 = a[j] + v[j];
                t0 = fmaf(rds, dw[j], t0);
                t0 = fmaf(rsp, sw[j], t0);
                x[j] = fmaxf(t0, 0.f);
            }
            uint4 o = make_uint4(pack_bf16x2(x[0], x[1]), pack_bf16x2(x[2], x[3]),
                                 pack_bf16x2(x[4], x[5]), pack_bf16x2(x[6], x[7]));
            *(uint4*)(hbufu + ((c + 1) & 1) * 64 * HP + ar * HP + acw * 4) = o;
        }

        // MMA on chunk c: hbuf[c&1], wbuf[c&1]
        const uint32_t* h1u = hbufu + (c & 1) * 64 * HP;
        const uint32_t* w2u = wbufu + (c & 1) * 16 * WP;
#pragma unroll
        for (int kp = 0; kp < KC / 2; kp += 8) {   // two k16 steps
            uint32_t a[2][4];
#pragma unroll
            for (int t = 0; t < 2; t++) {
                const int base = (mp * 32 + t * 16 + g) * HP + kp + tig;
                a[t][0] = h1u[base];
                a[t][1] = h1u[base + 8 * HP];
                a[t][2] = h1u[base + 4];
                a[t][3] = h1u[base + 8 * HP + 4];
            }
#pragma unroll
            for (int nt = 0; nt < 6; nt++) {
                const int col = nq * 48 + nt * 8 + g;
                const uint32_t b0 = w2u[(kp + tig) * WP + col];
                const uint32_t b1 = w2u[(kp + tig + 4) * WP + col];
                mma_bf16(acc[0][nt], a[0], b0, b1);
                mma_bf16(acc[1][nt], a[1], b0, b1);
            }
        }
    }

    // Layer 3: relu + dot W3 on fragments
    float pr2[2][2] = {{0.f, 0.f}, {0.f, 0.f}};
#pragma unroll
    for (int t = 0; t < 2; t++)
#pragma unroll
        for (int nt = 0; nt < 6; nt++) {
            const int col = nq * 48 + nt * 8 + 2 * tig;
            float h;
            h = fmaxf(acc[t][nt][0] + b2s[col],     0.f); pr2[t][0] = fmaf(h, w3s[col],     pr2[t][0]);
            h = fmaxf(acc[t][nt][1] + b2s[col + 1], 0.f); pr2[t][0] = fmaf(h, w3s[col + 1], pr2[t][0]);
            h = fmaxf(acc[t][nt][2] + b2s[col],     0.f); pr2[t][1] = fmaf(h, w3s[col],     pr2[t][1]);
            h = fmaxf(acc[t][nt][3] + b2s[col + 1], 0.f); pr2[t][1] = fmaf(h, w3s[col + 1], pr2[t][1]);
        }

#pragma unroll
    for (int t = 0; t < 2; t++)
#pragma unroll
        for (int hseg = 0; hseg < 2; hseg++) {
            pr2[t][hseg] += __shfl_xor_sync(0xffffffffu, pr2[t][hseg], 1);
            pr2[t][hseg] += __shfl_xor_sync(0xffffffffu, pr2[t][hseg], 2);
        }

    if (tig == 0) {
#pragma unroll
        for (int t = 0; t < 2; t++) {
            atomicAdd(&logits[mp * 32 + t * 16 + g],     pr2[t][0]);
            atomicAdd(&logits[mp * 32 + t * 16 + g + 8], pr2[t][1]);
        }
    }
    __syncthreads();

    if (tid < 64) {
        const float logit = logits[tid] + b3[0];
        const float wgt   = 1.f / (1.f + expf(-logit));
        out[q * DN + d0 + tid] = wgt * dss[tid] + (1.f - wgt) * sps[tid];
    }
}

// ---------------------------------------------------------------------------
extern "C" void kernel_launch(void* const* d_in, const int* in_sizes, int n_in,
                              void* d_out, int out_size)
{
    const float* qd = (const float*)d_in[0];
    const float* dd = (const float*)d_in[1];
    const float* sp = (const float*)d_in[2];
    const float* W1 = (const float*)d_in[3];
    const float* b1 = (const float*)d_in[4];
    const float* W2 = (const float*)d_in[5];
    const float* b2 = (const float*)d_in[6];
    const float* W3 = (const float*)d_in[7];
    const float* b3 = (const float*)d_in[8];
    float* out = (float*)d_out;

    const size_t smem3 = (size_t)(2 * 64 * HP + 2 * 16 * WP) * 4
                       + (size_t)(2 * 64 * GS + 3 * DIM + 2 * H2 + 3 * 64) * 4;
                       // = 35840 + 25344 = 61184 B

    cudaFuncSetAttribute(k_main, cudaFuncAttributeMaxDynamicSharedMemorySize, (int)smem3);

    k_cvtw2p<<<DIM / 2, 192>>>(W2);
    k_precompute<<<258, 256>>>(qd, dd, W1, b1);
    k_dense<<<128, 256>>>(qd, dd, sp, out);
    k_main<<<(QN * DN) / 64, 256, smem3>>>(W1, b2, W3, b3, sp, out);
}

// round 10
// speedup vs baseline: 4.5051x; 1.2481x over previous
#include <cuda_runtime.h>
#include <math.h>
#include <stdint.h>

#define QN  32
#define DN  4096
#define DIM 384
#define H2  192
#define KC    32          // K chunk (16 bf16 pairs)
#define NCH   12          // DIM / KC
#define HP    20          // hbuf row stride (u32 pairs): 16 + 4 pad, conflict-free
#define WP    200         // w2 pair-row stride (u32): 192 + 8 pad, conflict-free
#define GS    36          // gbstage row stride (floats): 32 + 4 pad
#define XP    196         // k_precompute X row stride (u32 pairs): 192 + 4 pad
#define WPP   200         // k_precompute W1 tile pair-row stride (u32)

// Scratch (device globals: allocation-free per harness rules)
__device__ float    g_B[DN * DIM];          // doc_dense @ W1[384:768]
__device__ float    g_A[QN * DIM];          // query_dense @ W1[0:384] + b1
__device__ uint32_t g_W2p[(DIM / 2) * H2];  // W2 packed bf16x2 along K: [pair][n]
__device__ uint32_t g_W1p[2 * 192 * DIM];   // W1 halves packed bf16x2: [hs][pair][j]

// ---------------------------------------------------------------------------
__device__ __forceinline__ uint32_t pack_bf16x2(float lo, float hi)
{
    uint32_t r;
    asm("cvt.rn.bf16x2.f32 %0, %1, %2;" : "=r"(r) : "f"(hi), "f"(lo));
    return r;
}

__device__ __forceinline__ void mma_bf16(float c[4], const uint32_t a[4],
                                         uint32_t b0, uint32_t b1)
{
    asm volatile(
        "mma.sync.aligned.m16n8k16.row.col.f32.bf16.bf16.f32 "
        "{%0,%1,%2,%3}, {%4,%5,%6,%7}, {%8,%9}, {%0,%1,%2,%3};\n"
        : "+f"(c[0]), "+f"(c[1]), "+f"(c[2]), "+f"(c[3])
        : "r"(a[0]), "r"(a[1]), "r"(a[2]), "r"(a[3]), "r"(b0), "r"(b1));
}

__device__ __forceinline__ void cp_async16(uint32_t dst_smem, const void* src)
{
    asm volatile("cp.async.cg.shared.global [%0], [%1], 16;\n"
                 :: "r"(dst_smem), "l"(src));
}
#define CP_COMMIT() asm volatile("cp.async.commit_group;\n" ::: "memory")
#define CP_WAIT0()  asm volatile("cp.async.wait_group 0;\n" ::: "memory")

// ---------------------------------------------------------------------------
// Kernel 0a: pack W2 (384x192 f32) into bf16x2 pairs along K.
// ---------------------------------------------------------------------------
__global__ void __launch_bounds__(192)
k_cvtw2p(const float* __restrict__ W2)
{
    const int p = blockIdx.x;    // 0..191
    const int n = threadIdx.x;   // 0..191
    g_W2p[p * H2 + n] = pack_bf16x2(W2[(2 * p) * H2 + n],
                                    W2[(2 * p + 1) * H2 + n]);
}

// ---------------------------------------------------------------------------
// Kernel 0b: pack W1 halves into bf16x2 pairs along K.
// g_W1p[hs*73728 + p*384 + j] = {W1[hs*384+2p][j], W1[hs*384+2p+1][j]}
// ---------------------------------------------------------------------------
__global__ void __launch_bounds__(384)
k_cvtw1p(const float* __restrict__ W1)
{
    const int b  = blockIdx.x;          // 0..383
    const int hs = b / 192;
    const int p  = b - hs * 192;
    const int j  = threadIdx.x;         // 0..383
    const int k0 = hs * 384 + 2 * p;
    g_W1p[hs * (192 * DIM) + p * DIM + j] =
        pack_bf16x2(W1[(size_t)k0 * DIM + j], W1[(size_t)(k0 + 1) * DIM + j]);
}

// ---------------------------------------------------------------------------
// Kernel 1: precompute A and B via bf16 mma (fp32 accum).
// 258 CTAs: blk<256 -> doc block (blk>>1)*32 rows, col half blk&1 (W1[384:768]).
//           blk 256/257 -> query rows, col half blk-256 (W1[0:384], +b1).
// M=32, N=192, K=384. X packed to bf16 in smem once; W1 tiles double-buffered
// via cp.async. Warp w: m-tile w&1 (16 rows), 48-col block w>>1, 6 n-tiles.
// ---------------------------------------------------------------------------
__global__ void __launch_bounds__(256, 4)
k_precompute(const float* __restrict__ qd,
             const float* __restrict__ dd,
             const float* __restrict__ b1)
{
    extern __shared__ uint32_t sp_[];
    uint32_t* xs  = sp_;                 // 32*XP  = 6272 u32
    uint32_t* wst = sp_ + 32 * XP;       // 2*16*WPP = 6400 u32

    uint32_t smem_b;
    asm("{ .reg .u64 t; cvta.to.shared.u64 t, %1; cvt.u32.u64 %0, t; }"
        : "=r"(smem_b) : "l"(sp_));
    const uint32_t wst_b = smem_b + 32 * XP * 4;

    const int tid = threadIdx.x;
    const int blk = blockIdx.x;

    const float* X;
    float* outp;
    int half, hs;
    bool isQ;
    if (blk < 256) {
        const int rb = blk >> 1;
        half = blk & 1;
        hs   = 1;
        X    = dd + (size_t)rb * 32 * DIM;
        outp = g_B + (size_t)rb * 32 * DIM;
        isQ  = false;
    } else {
        half = blk - 256;
        hs   = 0;
        X    = qd;
        outp = g_A;
        isQ  = true;
    }

    // pack X (32 x 384 f32) -> xs bf16 pairs [row][pair], stride XP
    const float2* X2 = (const float2*)X;
    for (int e = tid; e < 32 * 192; e += 256) {
        const int row = e / 192;
        const int p   = e - row * 192;
        const float2 v = X2[row * 192 + p];
        xs[row * XP + p] = pack_bf16x2(v.x, v.y);
    }

    // cp.async indexing for W1 tiles: 16 pair-rows x 192 cols per chunk
    const int wr = tid >> 4;                 // 0..15 pair-row in tile
    const int wc = (tid & 15) * 12;          // 12 u32 = 48B -> 3 cp16
    const uint32_t* wsrc0 = g_W1p + (size_t)hs * (192 * DIM) + half * 192;
    const uint32_t wdst0 = wst_b + (uint32_t)(wr * WPP + wc) * 4;

    // warp layout
    const int lane = tid & 31;
    const int w    = tid >> 5;
    const int g    = lane >> 2;
    const int tig  = lane & 3;
    const int mt   = w & 1;                  // 16-row tile
    const int nh   = w >> 1;                 // 48-col block (0..3)

    float acc[6][4];
#pragma unroll
    for (int nt = 0; nt < 6; nt++)
#pragma unroll
        for (int i = 0; i < 4; i++) acc[nt][i] = 0.f;

    // prologue: stage W1 chunk 0
    {
        const uint32_t* src = wsrc0 + wr * DIM + wc;
#pragma unroll
        for (int i = 0; i < 3; i++) cp_async16(wdst0 + i * 16, src + i * 4);
        CP_COMMIT();
    }

    for (int c = 0; c < NCH; c++) {
        CP_WAIT0();
        __syncthreads();   // W1 chunk c visible; xs packing done (c==0)

        if (c < NCH - 1) {
            const int pr = (c + 1) * 16;
            const uint32_t* src = wsrc0 + (size_t)(pr + wr) * DIM + wc;
            const uint32_t wdst = wdst0 + (uint32_t)(((c + 1) & 1) * 16 * WPP) * 4;
#pragma unroll
            for (int i = 0; i < 3; i++) cp_async16(wdst + i * 16, src + i * 4);
            CP_COMMIT();
        }

        const uint32_t* w1u = wst + (c & 1) * 16 * WPP;
#pragma unroll
        for (int kp = 0; kp < 16; kp += 8) {
            uint32_t a[4];
            const int base = (mt * 16 + g) * XP + c * 16 + kp + tig;
            a[0] = xs[base];
            a[1] = xs[base + 8 * XP];
            a[2] = xs[base + 4];
            a[3] = xs[base + 8 * XP + 4];
#pragma unroll
            for (int nt = 0; nt < 6; nt++) {
                const int col = nh * 48 + nt * 8 + g;
                const uint32_t b0 = w1u[(kp + tig) * WPP + col];
                const uint32_t b1v = w1u[(kp + tig + 4) * WPP + col];
                mma_bf16(acc[nt], a, b0, b1v);
            }
        }
    }

    // epilogue: store fp32 (add b1 for query CTAs)
    const int r0 = mt * 16 + g;
#pragma unroll
    for (int nt = 0; nt < 6; nt++) {
        const int ncol = nh * 48 + nt * 8 + 2 * tig;
        const int gcol = half * 192 + ncol;
        float c0 = acc[nt][0], c1 = acc[nt][1];
        float c2 = acc[nt][2], c3 = acc[nt][3];
        if (isQ) {
            const float bb0 = b1[gcol], bb1 = b1[gcol + 1];
            c0 += bb0; c1 += bb1; c2 += bb0; c3 += bb1;
        }
        *(float2*)(outp + (size_t)r0 * DIM + gcol)       = make_float2(c0, c1);
        *(float2*)(outp + (size_t)(r0 + 8) * DIM + gcol) = make_float2(c2, c3);
    }
}

// ---------------------------------------------------------------------------
// Kernel 2: dense_scores + sparse copy (fp32, exact).
// ---------------------------------------------------------------------------
__global__ void __launch_bounds__(256)
k_dense(const float* __restrict__ qd,
        const float* __restrict__ dd,
        const float* __restrict__ sparse,
        float* __restrict__ out)
{
    __shared__ float qs[16 * DIM];   // 24 KB

    const int tid = threadIdx.x;
    const int d0  = (blockIdx.x & 63) * 64;
    const int qh  = blockIdx.x >> 6;           // 0 or 1
    const float* qbase = qd + qh * 16 * DIM;

    for (int e = tid; e < 16 * DIM; e += 256) qs[e] = qbase[e];
    __syncthreads();

    const int tx = tid & 63;
    const int ty = tid >> 6;          // 0..3 -> 4 q's each
    const int d  = d0 + tx;
    const float* drow = dd + d * DIM;

    float acc[4];
#pragma unroll
    for (int i = 0; i < 4; i++) acc[i] = 0.f;

    for (int k = 0; k < DIM; k += 4) {
        const float4 dv4 = *(const float4*)(drow + k);
        const float dv[4] = {dv4.x, dv4.y, dv4.z, dv4.w};
#pragma unroll
        for (int t = 0; t < 4; t++)
#pragma unroll
            for (int i = 0; i < 4; i++)
                acc[i] = fmaf(qs[(ty * 4 + i) * DIM + k + t], dv[t], acc[i]);
    }

    float* outD = out + QN * DN;
    float* outS = out + 2 * QN * DN;
#pragma unroll
    for (int i = 0; i < 4; i++) {
        const int q   = qh * 16 + ty * 4 + i;
        const int idx = q * DN + d;
        outD[idx] = acc[i];
        outS[idx] = sparse[idx];
    }
}

// ---------------------------------------------------------------------------
// Kernel 3: main fused MLP (verified R9 version, unchanged).
// One CTA = 1 q x 64 docs, 256 threads, ~60KB smem -> 3 CTAs/SM.
// bf16 mma m16n8k16; hbuf double-buffered; W2 + g_B staged via cp.async.
// ---------------------------------------------------------------------------
__global__ void __launch_bounds__(256, 3)
k_main(const float* __restrict__ W1,
       const float* __restrict__ b2,
       const float* __restrict__ W3,
       const float* __restrict__ b3,
       const float* __restrict__ sparse,
       float* __restrict__ out)
{
    extern __shared__ float s3[];
    uint32_t* hbufu = (uint32_t*)s3;            // 2 * 64*HP   = 2560 u32
    uint32_t* wbufu = hbufu + 2 * 64 * HP;      // 2 * 16*WP   = 6400 u32
    float* gbst     = (float*)(wbufu + 2 * 16 * WP);  // 2 * 64*GS = 4608 f
    float* As       = gbst + 2 * 64 * GS;       // 384
    float* wds      = As  + DIM;                // 384
    float* wsp      = wds + DIM;                // 384
    float* b2s      = wsp + DIM;                // 192
    float* w3s      = b2s + H2;                 // 192
    float* dss      = w3s + H2;                 // 64
    float* sps      = dss + 64;                 // 64
    float* logits   = sps + 64;                 // 64

    uint32_t smem_u32;
    asm("{ .reg .u64 t; cvta.to.shared.u64 t, %1; cvt.u32.u64 %0, t; }"
        : "=r"(smem_u32) : "l"(s3));
    const uint32_t wbuf_b = smem_u32 + (2 * 64 * HP) * 4;
    const uint32_t gbst_b = smem_u32 + (2 * 64 * HP + 2 * 16 * WP) * 4;

    const int tid = threadIdx.x;
    const int blk = blockIdx.x;
    const int q   = blk >> 6;
    const int d0  = (blk & 63) << 6;
    const float* outD = out + QN * DN;

    for (int e = tid; e < DIM; e += 256) {
        As[e]  = g_A[q * DIM + e];
        wds[e] = W1[768 * DIM + e];
        wsp[e] = W1[769 * DIM + e];
    }
    if (tid < H2) { b2s[tid] = b2[tid]; w3s[tid] = W3[tid]; }
    if (tid < 64) {
        const int idx = q * DN + d0 + tid;
        dss[tid] = outD[idx];
        sps[tid] = sparse[idx];
        logits[tid] = 0.f;
    }
    __syncthreads();

    // ---- per-thread Phase-A indexing ----
    const int ar  = tid >> 2;               // 0..63 doc row
    const int acw = tid & 3;                // col quarter (8 cols / 4 pairs)
    const float rds = dss[ar];
    const float rsp = sps[ar];

    // ---- cp.async indexing ----
    const int wr = tid >> 4;                // 0..15 W2 pair-row
    const int wc = (tid & 15) * 12;         // 12 u32 = 48B -> 3 cp16
    const int gr = tid >> 2;                // 0..63 g_B row
    const int gc = (tid & 3) * 8;           // 8 floats = 32B -> 2 cp16
    const float* gB_base = g_B + (size_t)(d0 + gr) * DIM + gc;

    // ---- MMA warp layout ----
    const int lane = tid & 31;
    const int w    = tid >> 5;
    const int g    = lane >> 2;
    const int tig  = lane & 3;
    const int mp   = w & 1;                 // row half (32 rows)
    const int nq   = w >> 1;                // 48-col quarter

    float acc[2][6][4];
#pragma unroll
    for (int t = 0; t < 2; t++)
#pragma unroll
        for (int nt = 0; nt < 6; nt++)
#pragma unroll
            for (int i = 0; i < 4; i++) acc[t][nt][i] = 0.f;

    // ---- prologue: issue cp group {W2(0)->wbuf0, gB(1)->gbst1}, build h0 ----
    {
        const uint32_t* srcw = g_W2p + wr * H2 + wc;      // chunk 0 pairs
        const uint32_t wdst = wbuf_b + (uint32_t)(wr * WP + wc) * 4;
#pragma unroll
        for (int i = 0; i < 3; i++) cp_async16(wdst + i * 16, srcw + i * 4);
        const float* srcg = gB_base + KC;                 // chunk 1 cols
        const uint32_t gdst = gbst_b + (uint32_t)(64 * GS + gr * GS + gc) * 4;
        cp_async16(gdst,      srcg);
        cp_async16(gdst + 16, srcg + 4);
        CP_COMMIT();

        // build h chunk 0 from g_B directly (LDG)
        const float* gb = g_B + (size_t)(d0 + ar) * DIM + acw * 8;
        const float4 va = *(const float4*)gb;
        const float4 vb = *(const float4*)(gb + 4);
        const int col0 = acw * 8;
        const float4 A0 = *(const float4*)(As + col0);
        const float4 A1 = *(const float4*)(As + col0 + 4);
        const float4 D0 = *(const float4*)(wds + col0);
        const float4 D1 = *(const float4*)(wds + col0 + 4);
        const float4 S0 = *(const float4*)(wsp + col0);
        const float4 S1 = *(const float4*)(wsp + col0 + 4);
        const float v[8] = {va.x, va.y, va.z, va.w, vb.x, vb.y, vb.z, vb.w};
        const float a[8] = {A0.x, A0.y, A0.z, A0.w, A1.x, A1.y, A1.z, A1.w};
        const float dw[8] = {D0.x, D0.y, D0.z, D0.w, D1.x, D1.y, D1.z, D1.w};
        const float sw[8] = {S0.x, S0.y, S0.z, S0.w, S1.x, S1.y, S1.z, S1.w};
        float x[8];
#pragma unroll
        for (int j = 0; j < 8; j++) {
            float t0 = a[j] + v[j];
            t0 = fmaf(rds, dw[j], t0);
            t0 = fmaf(rsp, sw[j], t0);
            x[j] = fmaxf(t0, 0.f);
        }
        uint4 o = make_uint4(pack_bf16x2(x[0], x[1]), pack_bf16x2(x[2], x[3]),
                             pack_bf16x2(x[4], x[5]), pack_bf16x2(x[6], x[7]));
        *(uint4*)(hbufu + ar * HP + acw * 4) = o;
    }

    for (int c = 0; c < NCH; c++) {
        CP_WAIT0();
        __syncthreads();   // prev cp visible + all builds/MMAs of prev iter done

        // issue cp for W2(c+1) and gB(c+2)
        if (c < NCH - 1) {
            const int pr = (c + 1) * (KC / 2);   // pair base of chunk c+1
            const uint32_t* srcw = g_W2p + (pr + wr) * H2 + wc;
            const uint32_t wdst = wbuf_b
                + (uint32_t)(((c + 1) & 1) * 16 * WP + wr * WP + wc) * 4;
#pragma unroll
            for (int i = 0; i < 3; i++) cp_async16(wdst + i * 16, srcw + i * 4);
            if (c < NCH - 2) {
                const float* srcg = gB_base + (c + 2) * KC;
                const uint32_t gdst = gbst_b
                    + (uint32_t)(((c + 2) & 1) * 64 * GS + gr * GS + gc) * 4;
                cp_async16(gdst,      srcg);
                cp_async16(gdst + 16, srcg + 4);
            }
            CP_COMMIT();
        }

        // build h chunk c+1 into hbuf[(c+1)&1] from gbst[(c+1)&1]
        if (c < NCH - 1) {
            const float* gs = gbst + ((c + 1) & 1) * 64 * GS + ar * GS + acw * 8;
            const float4 va = ((const float4*)gs)[0];
            const float4 vb = ((const float4*)gs)[1];
            const int col0 = (c + 1) * KC + acw * 8;
            const float4 A0 = *(const float4*)(As + col0);
            const float4 A1 = *(const float4*)(As + col0 + 4);
            const float4 D0 = *(const float4*)(wds + col0);
            const float4 D1 = *(const float4*)(wds + col0 + 4);
            const float4 S0 = *(const float4*)(wsp + col0);
            const float4 S1 = *(const float4*)(wsp + col0 + 4);
            const float v[8] = {va.x, va.y, va.z, va.w, vb.x, vb.y, vb.z, vb.w};
            const float a[8] = {A0.x, A0.y, A0.z, A0.w, A1.x, A1.y, A1.z, A1.w};
            const float dw[8] = {D0.x, D0.y, D0.z, D0.w, D1.x, D1.y, D1.z, D1.w};
            const float sw[8] = {S0.x, S0.y, S0.z, S0.w, S1.x, S1.y, S1.z, S1.w};
            float x[8];
#pragma unroll
            for (int j = 0; j < 8; j++) {
                float t0 = a[j] + v[j];
                t0 = fmaf(rds, dw[j], t0);
                t0 = fmaf(rsp, sw[j], t0);
                x[j] = fmaxf(t0, 0.f);
            }
            uint4 o = make_uint4(pack_bf16x2(x[0], x[1]), pack_bf16x2(x[2], x[3]),
                                 pack_bf16x2(x[4], x[5]), pack_bf16x2(x[6], x[7]));
            *(uint4*)(hbufu + ((c + 1) & 1) * 64 * HP + ar * HP + acw * 4) = o;
        }

        // MMA on chunk c: hbuf[c&1], wbuf[c&1]
        const uint32_t* h1u = hbufu + (c & 1) * 64 * HP;
        const uint32_t* w2u = wbufu + (c & 1) * 16 * WP;
#pragma unroll
        for (int kp = 0; kp < KC / 2; kp += 8) {   // two k16 steps
            uint32_t a[2][4];
#pragma unroll
            for (int t = 0; t < 2; t++) {
                const int base = (mp * 32 + t * 16 + g) * HP + kp + tig;
                a[t][0] = h1u[base];
                a[t][1] = h1u[base + 8 * HP];
                a[t][2] = h1u[base + 4];
                a[t][3] = h1u[base + 8 * HP + 4];
            }
#pragma unroll
            for (int nt = 0; nt < 6; nt++) {
                const int col = nq * 48 + nt * 8 + g;
                const uint32_t b0 = w2u[(kp + tig) * WP + col];
                const uint32_t b1 = w2u[(kp + tig + 4) * WP + col];
                mma_bf16(acc[0][nt], a[0], b0, b1);
                mma_bf16(acc[1][nt], a[1], b0, b1);
            }
        }
    }

    // Layer 3: relu + dot W3 on fragments
    float pr2[2][2] = {{0.f, 0.f}, {0.f, 0.f}};
#pragma unroll
    for (int t = 0; t < 2; t++)
#pragma unroll
        for (int nt = 0; nt < 6; nt++) {
            const int col = nq * 48 + nt * 8 + 2 * tig;
            float h;
            h = fmaxf(acc[t][nt][0] + b2s[col],     0.f); pr2[t][0] = fmaf(h, w3s[col],     pr2[t][0]);
            h = fmaxf(acc[t][nt][1] + b2s[col + 1], 0.f); pr2[t][0] = fmaf(h, w3s[col + 1], pr2[t][0]);
            h = fmaxf(acc[t][nt][2] + b2s[col],     0.f); pr2[t][1] = fmaf(h, w3s[col],     pr2[t][1]);
            h = fmaxf(acc[t][nt][3] + b2s[col + 1], 0.f); pr2[t][1] = fmaf(h, w3s[col + 1], pr2[t][1]);
        }

#pragma unroll
    for (int t = 0; t < 2; t++)
#pragma unroll
        for (int hseg = 0; hseg < 2; hseg++) {
            pr2[t][hseg] += __shfl_xor_sync(0xffffffffu, pr2[t][hseg], 1);
            pr2[t][hseg] += __shfl_xor_sync(0xffffffffu, pr2[t][hseg], 2);
        }

    if (tig == 0) {
#pragma unroll
        for (int t = 0; t < 2; t++) {
            atomicAdd(&logits[mp * 32 + t * 16 + g],     pr2[t][0]);
            atomicAdd(&logits[mp * 32 + t * 16 + g + 8], pr2[t][1]);
        }
    }
    __syncthreads();

    if (tid < 64) {
        const float logit = logits[tid] + b3[0];
        const float wgt   = 1.f / (1.f + expf(-logit));
        out[q * DN + d0 + tid] = wgt * dss[tid] + (1.f - wgt) * sps[tid];
    }
}

// ---------------------------------------------------------------------------
extern "C" void kernel_launch(void* const* d_in, const int* in_sizes, int n_in,
                              void* d_out, int out_size)
{
    const float* qd = (const float*)d_in[0];
    const float* dd = (const float*)d_in[1];
    const float* sp = (const float*)d_in[2];
    const float* W1 = (const float*)d_in[3];
    const float* b1 = (const float*)d_in[4];
    const float* W2 = (const float*)d_in[5];
    const float* b2 = (const float*)d_in[6];
    const float* W3 = (const float*)d_in[7];
    const float* b3 = (const float*)d_in[8];
    float* out = (float*)d_out;

    const size_t smemP = (size_t)(32 * XP + 2 * 16 * WPP) * 4;   // 50,688 B
    const size_t smem3 = (size_t)(2 * 64 * HP + 2 * 16 * WP) * 4
                       + (size_t)(2 * 64 * GS + 3 * DIM + 2 * H2 + 3 * 64) * 4;
                       // = 61,184 B

    cudaFuncSetAttribute(k_precompute, cudaFuncAttributeMaxDynamicSharedMemorySize, (int)smemP);
    cudaFuncSetAttribute(k_main,       cudaFuncAttributeMaxDynamicSharedMemorySize, (int)smem3);

    k_cvtw2p<<<DIM / 2, 192>>>(W2);
    k_cvtw1p<<<384, 384>>>(W1);
    k_precompute<<<258, 256, smemP>>>(qd, dd, b1);
    k_dense<<<128, 256>>>(qd, dd, sp, out);
    k_main<<<(QN * DN) / 64, 256, smem3>>>(W1, b2, W3, b3, sp, out);
}